// round 15
// baseline (speedup 1.0000x reference)
#include <cuda_runtime.h>
#include <cuda_bf16.h>
#include <cstdint>
#include <math.h>

#define NPTS    524288
#define NGRIDS  64
#define GVOX    262144      /* 64^3 */
#define PE_L    6
#define NBUCK   32768       /* 15-bit Morton buckets (32^3) */
#define THREADS 192
#define PTS_CTA 192
#define NBLKS   ((NPTS + PTS_CTA - 1) / PTS_CTA)

// x-duplicated channel-interleaved volumes (256 MB)
__device__ float4 g_dupx[NGRIDS * GVOX];
__device__ int    g_hist[NBUCK];
__device__ int    g_off[NBUCK];
__device__ int    g_bsum[128];
__device__ int    g_boff[128];
__device__ int    g_perm[NPTS];
__device__ unsigned long long g_mask[NPTS];

// ---------------- packed f32x2 helpers ----------------
__device__ __forceinline__ void fma2(unsigned long long& d,
                                     unsigned long long a,
                                     unsigned long long b) {
    asm("fma.rn.f32x2 %0, %1, %2, %0;" : "+l"(d) : "l"(a), "l"(b));
}
__device__ __forceinline__ unsigned long long bcast2(float f) {
    unsigned long long r;
    asm("mov.b64 %0, {%1, %2};" : "=l"(r) : "f"(f), "f"(f));
    return r;
}
__device__ __forceinline__ float2 unpack2(unsigned long long v) {
    float2 f;
    asm("mov.b64 {%0, %1}, %2;" : "=f"(f.x), "=f"(f.y) : "l"(v));
    return f;
}
__device__ __forceinline__ unsigned long long pack2(float a, float b) {
    unsigned long long r;
    asm("mov.b64 %0, {%1, %2};" : "=l"(r) : "f"(a), "f"(b));
    return r;
}
// acc[0..31] += f * row[0..63] from shared memory (broadcast)
__device__ __forceinline__ void accum_row_s(unsigned long long* acc,
                                            const float* row, float f) {
    unsigned long long ff = bcast2(f);
    const ulonglong2* r2 = reinterpret_cast<const ulonglong2*>(row);
#pragma unroll
    for (int i = 0; i < 16; i++) {
        ulonglong2 w = r2[i];
        fma2(acc[2 * i], ff, w.x);
        fma2(acc[2 * i + 1], ff, w.y);
    }
}
// 15-bit Morton key from 5-bit coords
__device__ __forceinline__ int morton_key(float px, float py, float pz) {
    int qx = min(max((int)((px + 1.f) * 16.f), 0), 31);
    int qy = min(max((int)((py + 1.f) * 16.f), 0), 31);
    int qz = min(max((int)((pz + 1.f) * 16.f), 0), 31);
    int r = 0;
#pragma unroll
    for (int i = 0; i < 5; i++) {
        r |= ((qx >> i) & 1) << (3 * i + 2);
        r |= ((qy >> i) & 1) << (3 * i + 1);
        r |= ((qz >> i) & 1) << (3 * i + 0);
    }
    return r;
}

// ---------------- repack: one voxel per thread, coalesced ----------------
__global__ void repack_dup(const float* __restrict__ fg) {
    int idx = blockIdx.x * blockDim.x + threadIdx.x;   // 0 .. 16777215
    int g = idx >> 18;
    int v = idx & (GVOX - 1);
    const float* f0p = fg + (size_t)(2 * g) * GVOX;
    const float* f1p = fg + (size_t)(2 * g + 1) * GVOX;
    float a = f0p[v];
    float b = f1p[v];
    float an = __shfl_down_sync(0xffffffffu, a, 1);
    float bn = __shfl_down_sync(0xffffffffu, b, 1);
    int xq = v & 63;
    if (xq == 63) { an = a; bn = b; }
    else if ((threadIdx.x & 31) == 31) {
        an = f0p[v + 1];
        bn = f1p[v + 1];
    }
    g_dupx[idx] = make_float4(a, b, an, bn);
}

// ---------------- sort pipeline ----------------
__global__ void zero_hist() {
    g_hist[blockIdx.x * blockDim.x + threadIdx.x] = 0;
}
__global__ void hist_kernel(const float* __restrict__ x) {
    int pt = blockIdx.x * blockDim.x + threadIdx.x;
    int k = morton_key(x[3 * pt], x[3 * pt + 1], x[3 * pt + 2]);
    atomicAdd(&g_hist[k], 1);
}
// phase A: per-block exclusive scan of 256 buckets + block total
__global__ void scanA() {
    __shared__ int s[256];
    int t = threadIdx.x;
    int i = blockIdx.x * 256 + t;
    int v = g_hist[i];
    s[t] = v;
    __syncthreads();
#pragma unroll
    for (int d = 1; d < 256; d <<= 1) {
        int u = (t >= d) ? s[t - d] : 0;
        __syncthreads();
        s[t] += u;
        __syncthreads();
    }
    g_off[i] = s[t] - v;                 // exclusive within block
    if (t == 255) g_bsum[blockIdx.x] = s[255];
}
// phase B: scan the 128 block totals (1 block, 128 threads)
__global__ void scanB() {
    __shared__ int s[128];
    int t = threadIdx.x;
    int v = g_bsum[t];
    s[t] = v;
    __syncthreads();
#pragma unroll
    for (int d = 1; d < 128; d <<= 1) {
        int u = (t >= d) ? s[t - d] : 0;
        __syncthreads();
        s[t] += u;
        __syncthreads();
    }
    g_boff[t] = s[t] - v;                // exclusive block offset
}
// phase C: add block offsets
__global__ void scanC() {
    int i = blockIdx.x * 256 + threadIdx.x;
    g_off[i] += g_boff[blockIdx.x];
}
// scatter + per-point validity mask precompute
__global__ void scatter_kernel(const float* __restrict__ x,
                               const float* __restrict__ gscale,
                               const float* __restrict__ gtrans) {
    __shared__ float sc[192], tr[192];
    const int tid = threadIdx.x;
    for (int i = tid; i < 192; i += 256) {
        sc[i] = gscale[i];
        tr[i] = gtrans[i];
    }
    __syncthreads();
    int pt = blockIdx.x * blockDim.x + tid;
    float px = x[3 * pt], py = x[3 * pt + 1], pz = x[3 * pt + 2];
    int k = morton_key(px, py, pz);
    int pos = atomicAdd(&g_off[k], 1);
    g_perm[pos] = pt;
    unsigned long long mask = 0ull;
#pragma unroll 1
    for (int g = 0; g < 64; g++) {
        float ix = fmaf(fmaf(px, sc[3 * g + 0], tr[3 * g + 0]), 31.5f, 31.5f);
        float iy = fmaf(fmaf(py, sc[3 * g + 1], tr[3 * g + 1]), 31.5f, 31.5f);
        float iz = fmaf(fmaf(pz, sc[3 * g + 2], tr[3 * g + 2]), 31.5f, 31.5f);
        if (ix > -1.f && ix < 64.f && iy > -1.f && iy < 64.f && iz > -1.f &&
            iz < 64.f)
            mask |= 1ull << g;
    }
    g_mask[pt] = mask;
}

// ---------------- smem layout (floats), identical to R14 ----------------
#define OFF_PE   0                        // 36*64 = 2304
#define OFF_W0G  (OFF_PE + 36 * 64)       // 64*132 = 8448
#define OFF_W1T  (OFF_W0G + 64 * 132)     // 64*64 = 4096
#define OFF_W2   (OFF_W1T + 64 * 64)      // 64
#define OFF_B1   (OFF_W2 + 64)            // 64
#define OFF_B0   (OFF_B1 + 64)            // 64
#define OFF_GP   (OFF_B0 + 64)            // 512
#define SMEM_FLOATS (OFF_GP + 512)
#define SMEM_BYTES  (SMEM_FLOATS * 4)     // ~62 KB -> 3 CTAs/SM (187 KB)

__global__ void __launch_bounds__(THREADS, 3)
amrsrn_main(const float* __restrict__ x,
            const float* __restrict__ gscale,
            const float* __restrict__ gtrans,
            const float* __restrict__ W0,
            const float* __restrict__ b0,
            const float* __restrict__ W1,
            const float* __restrict__ b1,
            const float* __restrict__ W2,
            const float* __restrict__ b2,
            float* __restrict__ out) {
    extern __shared__ float sm[];
    int tid = threadIdx.x;

    // ---- stage weights ----
    for (int i = tid; i < 36 * 64; i += THREADS) sm[OFF_PE + i] = W0[i];
    for (int i = tid; i < 64 * 128; i += THREADS) {
        int g = i >> 7, j = i & 127;
        int row = 36 + 2 * g + (j >> 6);
        sm[OFF_W0G + g * 132 + j] = W0[row * 64 + (j & 63)];
    }
    for (int i = tid; i < 64 * 64; i += THREADS) {   // transpose W1 -> [k][j]
        int j = i >> 6, k = i & 63;
        sm[OFF_W1T + k * 64 + j] = W1[i];
    }
    for (int i = tid; i < 64; i += THREADS) {
        sm[OFF_W2 + i] = W2[i];
        sm[OFF_B1 + i] = b1[i];
        sm[OFF_B0 + i] = b0[i];
    }
    for (int i = tid; i < 64; i += THREADS) {
        sm[OFF_GP + i * 8 + 0] = gscale[3 * i + 0];
        sm[OFF_GP + i * 8 + 1] = gscale[3 * i + 1];
        sm[OFF_GP + i * 8 + 2] = gscale[3 * i + 2];
        sm[OFF_GP + i * 8 + 3] = gtrans[3 * i + 0];
        sm[OFF_GP + i * 8 + 4] = gtrans[3 * i + 1];
        sm[OFF_GP + i * 8 + 5] = gtrans[3 * i + 2];
        sm[OFF_GP + i * 8 + 6] = 0.f;
        sm[OFF_GP + i * 8 + 7] = 0.f;
    }
    __syncthreads();

    const int slot = blockIdx.x * PTS_CTA + tid;
    if (slot >= NPTS) return;           // partial last block (after barrier)

    const int pt = g_perm[slot];
    unsigned long long mask = __ldg(&g_mask[pt]);
    const float px = __ldg(&x[3 * pt + 0]);
    const float py = __ldg(&x[3 * pt + 1]);
    const float pz = __ldg(&x[3 * pt + 2]);
    const float xyz[3] = {px, py, pz};
    const float4* gp4 = (const float4*)&sm[OFF_GP];

    // ---- h0 accumulators (32 packed f32x2), init = b0 ----
    unsigned long long acc[32];
    const unsigned long long* pb0 =
        reinterpret_cast<const unsigned long long*>(&sm[OFF_B0]);
#pragma unroll
    for (int i = 0; i < 32; i++) acc[i] = pb0[i];

    // ---- PE via double-angle recurrence (smem broadcast rows) ----
#pragma unroll
    for (int d = 0; d < 3; d++) {
        float s, c;
        sincosf(xyz[d] * 3.14159265358979323846f, &s, &c);
#pragma unroll
        for (int l = 0; l < PE_L; l++) {
            accum_row_s(acc, &sm[OFF_PE + (l * 3 + d) * 64], s);
            accum_row_s(acc, &sm[OFF_PE + (18 + l * 3 + d) * 64], c);
            float s2 = 2.f * s * c;
            float c2 = fmaf(-2.f * s, s, 1.f);
            s = s2;
            c = c2;
        }
    }

    // ---- compacted sparse gather + accumulation (mask precomputed) ----
    while (mask) {
        int g = __ffsll((long long)mask) - 1;
        mask &= mask - 1;
        float4 p1 = gp4[g * 2];
        float4 p2 = gp4[g * 2 + 1];
        float ix = fmaf(fmaf(px, p1.x, p1.w), 31.5f, 31.5f);
        float iy = fmaf(fmaf(py, p1.y, p2.x), 31.5f, 31.5f);
        float iz = fmaf(fmaf(pz, p1.z, p2.y), 31.5f, 31.5f);
        float fx = floorf(ix), fy = floorf(iy), fz = floorf(iz);
        int X0 = (int)fx, Y0 = (int)fy, Z0 = (int)fz;
        float wx1 = ix - fx, wy1 = iy - fy, wz1 = iz - fz;
        float wx0 = 1.f - wx1, wy0 = 1.f - wy1, wz0 = 1.f - wz1;
        int bx = X0;
        float wa = wx0, wb = wx1;
        if (X0 < 0)        { bx = 0; wa = wx1; wb = 0.f; }
        else if (X0 >= 63) { wb = 0.f; }
        if (Y0 < 0)   wy0 = 0.f;
        if (Y0 >= 63) wy1 = 0.f;
        if (Z0 < 0)   wz0 = 0.f;
        if (Z0 >= 63) wz1 = 0.f;
        int y0c = max(Y0, 0), y1c = min(Y0 + 1, 63);
        int z0c = max(Z0, 0), z1c = min(Z0 + 1, 63);

        const float4* vol = g_dupx + ((size_t)g << 18);
        float4 q00 = __ldg(&vol[(z0c << 12) + (y0c << 6) + bx]);
        float4 q01 = __ldg(&vol[(z0c << 12) + (y1c << 6) + bx]);
        float4 q10 = __ldg(&vol[(z1c << 12) + (y0c << 6) + bx]);
        float4 q11 = __ldg(&vol[(z1c << 12) + (y1c << 6) + bx]);

        float w00 = wz0 * wy0, w01 = wz0 * wy1;
        float w10 = wz1 * wy0, w11 = wz1 * wy1;

        float r00 = fmaf(wb, q00.z, wa * q00.x);
        float r01 = fmaf(wb, q01.z, wa * q01.x);
        float r10 = fmaf(wb, q10.z, wa * q10.x);
        float r11 = fmaf(wb, q11.z, wa * q11.x);
        float f0 = w00 * r00;
        f0 = fmaf(w01, r01, f0);
        f0 = fmaf(w10, r10, f0);
        f0 = fmaf(w11, r11, f0);

        float s00 = fmaf(wb, q00.w, wa * q00.y);
        float s01 = fmaf(wb, q01.w, wa * q01.y);
        float s10 = fmaf(wb, q10.w, wa * q10.y);
        float s11 = fmaf(wb, q11.w, wa * q11.y);
        float f1 = w00 * s00;
        f1 = fmaf(w01, s01, f1);
        f1 = fmaf(w10, s10, f1);
        f1 = fmaf(w11, s11, f1);

        const float* wrow = &sm[OFF_W0G + g * 132];
        accum_row_s(acc, wrow, f0);
        accum_row_s(acc, wrow + 64, f1);
    }

    // ---- snake activation on h0 ----
#pragma unroll
    for (int i = 0; i < 32; i++) {
        float2 h = unpack2(acc[i]);
        float s0 = __sinf(h.x), s1 = __sinf(h.y);
        acc[i] = pack2(fmaf(0.5f, h.x, s0 * s0), fmaf(0.5f, h.y, s1 * s1));
    }

    // ---- layer1 (smem broadcast W1T rows) + snake + layer2 ----
    float outv = 0.f;
#pragma unroll 1
    for (int k = 0; k < 64; k++) {
        const ulonglong2* r2 =
            reinterpret_cast<const ulonglong2*>(&sm[OFF_W1T + k * 64]);
        unsigned long long a0 = 0ull, a1 = 0ull, a2 = 0ull, a3 = 0ull;
#pragma unroll
        for (int j = 0; j < 8; j++) {
            ulonglong2 wA = r2[2 * j];
            ulonglong2 wB = r2[2 * j + 1];
            fma2(a0, acc[4 * j + 0], wA.x);
            fma2(a1, acc[4 * j + 1], wA.y);
            fma2(a2, acc[4 * j + 2], wB.x);
            fma2(a3, acc[4 * j + 3], wB.y);
        }
        float2 fa = unpack2(a0), fb = unpack2(a1), fc = unpack2(a2),
               fd = unpack2(a3);
        float h = ((fa.x + fa.y) + (fb.x + fb.y)) +
                  ((fc.x + fc.y) + (fd.x + fd.y)) + sm[OFF_B1 + k];
        float s = __sinf(h);
        outv = fmaf(fmaf(0.5f, h, s * s), sm[OFF_W2 + k], outv);
    }

    out[pt] = outv + __ldg(b2);
}

extern "C" void kernel_launch(void* const* d_in, const int* in_sizes, int n_in,
                              void* d_out, int out_size) {
    const float* x      = (const float*)d_in[0];
    const float* gsc    = (const float*)d_in[1];
    const float* gtr    = (const float*)d_in[2];
    const float* fgrids = (const float*)d_in[3];
    const float* W0     = (const float*)d_in[4];
    const float* b0     = (const float*)d_in[5];
    const float* W1     = (const float*)d_in[6];
    const float* b1     = (const float*)d_in[7];
    const float* W2     = (const float*)d_in[8];
    const float* b2     = (const float*)d_in[9];
    float* out          = (float*)d_out;

    cudaFuncSetAttribute(amrsrn_main,
                         cudaFuncAttributeMaxDynamicSharedMemorySize,
                         SMEM_BYTES);

    repack_dup<<<(NGRIDS * GVOX) / 256, 256>>>(fgrids);
    zero_hist<<<NBUCK / 256, 256>>>();
    hist_kernel<<<NPTS / 256, 256>>>(x);
    scanA<<<128, 256>>>();
    scanB<<<1, 128>>>();
    scanC<<<128, 256>>>();
    scatter_kernel<<<NPTS / 256, 256>>>(x, gsc, gtr);
    amrsrn_main<<<NBLKS, THREADS, SMEM_BYTES>>>(x, gsc, gtr, W0, b0, W1, b1,
                                                W2, b2, out);
}

// round 16
// speedup vs baseline: 1.2447x; 1.2447x over previous
#include <cuda_runtime.h>
#include <cuda_bf16.h>
#include <cstdint>
#include <math.h>

#define NPTS    524288
#define NGRIDS  64
#define GVOX    262144      /* 64^3 */
#define PE_L    6
#define NBUCK   262144      /* 18-bit Morton buckets (64^3) */
#define NTILE   1024        /* NBUCK / 256 scan tiles */
#define THREADS 256
#define PTS_CTA 256

// x-duplicated channel-interleaved volumes (256 MB)
__device__ float4 g_dupx[NGRIDS * GVOX];
__device__ int    g_hist[NBUCK];
__device__ int    g_off[NBUCK];
__device__ int    g_bsum[NTILE];
__device__ int    g_boff[NTILE];
__device__ float4 g_xs[NPTS];                 // sorted {x,y,z, bits(pt)}
__device__ unsigned long long g_msort[NPTS];  // sorted validity masks

// ---------------- packed f32x2 helpers ----------------
__device__ __forceinline__ void fma2(unsigned long long& d,
                                     unsigned long long a,
                                     unsigned long long b) {
    asm("fma.rn.f32x2 %0, %1, %2, %0;" : "+l"(d) : "l"(a), "l"(b));
}
__device__ __forceinline__ unsigned long long bcast2(float f) {
    unsigned long long r;
    asm("mov.b64 %0, {%1, %2};" : "=l"(r) : "f"(f), "f"(f));
    return r;
}
__device__ __forceinline__ float2 unpack2(unsigned long long v) {
    float2 f;
    asm("mov.b64 {%0, %1}, %2;" : "=f"(f.x), "=f"(f.y) : "l"(v));
    return f;
}
__device__ __forceinline__ unsigned long long pack2(float a, float b) {
    unsigned long long r;
    asm("mov.b64 %0, {%1, %2};" : "=l"(r) : "f"(a), "f"(b));
    return r;
}
// acc[0..31] += f * row[0..63] from shared memory (broadcast)
__device__ __forceinline__ void accum_row_s(unsigned long long* acc,
                                            const float* row, float f) {
    unsigned long long ff = bcast2(f);
    const ulonglong2* r2 = reinterpret_cast<const ulonglong2*>(row);
#pragma unroll
    for (int i = 0; i < 16; i++) {
        ulonglong2 w = r2[i];
        fma2(acc[2 * i], ff, w.x);
        fma2(acc[2 * i + 1], ff, w.y);
    }
}
// 18-bit Morton key from 6-bit coords
__device__ __forceinline__ int morton_key(float px, float py, float pz) {
    int qx = min(max((int)((px + 1.f) * 32.f), 0), 63);
    int qy = min(max((int)((py + 1.f) * 32.f), 0), 63);
    int qz = min(max((int)((pz + 1.f) * 32.f), 0), 63);
    int r = 0;
#pragma unroll
    for (int i = 0; i < 6; i++) {
        r |= ((qx >> i) & 1) << (3 * i + 2);
        r |= ((qy >> i) & 1) << (3 * i + 1);
        r |= ((qz >> i) & 1) << (3 * i + 0);
    }
    return r;
}

// ---------------- repack: one voxel per thread, coalesced ----------------
__global__ void repack_dup(const float* __restrict__ fg) {
    int idx = blockIdx.x * blockDim.x + threadIdx.x;   // 0 .. 16777215
    int g = idx >> 18;
    int v = idx & (GVOX - 1);
    const float* f0p = fg + (size_t)(2 * g) * GVOX;
    const float* f1p = fg + (size_t)(2 * g + 1) * GVOX;
    float a = f0p[v];
    float b = f1p[v];
    float an = __shfl_down_sync(0xffffffffu, a, 1);
    float bn = __shfl_down_sync(0xffffffffu, b, 1);
    int xq = v & 63;
    if (xq == 63) { an = a; bn = b; }
    else if ((threadIdx.x & 31) == 31) {
        an = f0p[v + 1];
        bn = f1p[v + 1];
    }
    g_dupx[idx] = make_float4(a, b, an, bn);
}

// ---------------- sort pipeline ----------------
__global__ void zero_hist() {
    g_hist[blockIdx.x * blockDim.x + threadIdx.x] = 0;
}
__global__ void hist_kernel(const float* __restrict__ x) {
    int pt = blockIdx.x * blockDim.x + threadIdx.x;
    int k = morton_key(x[3 * pt], x[3 * pt + 1], x[3 * pt + 2]);
    atomicAdd(&g_hist[k], 1);
}
// phase A: per-tile exclusive scan of 256 buckets + tile total
__global__ void scanA() {
    __shared__ int s[256];
    int t = threadIdx.x;
    int i = blockIdx.x * 256 + t;
    int v = g_hist[i];
    s[t] = v;
    __syncthreads();
#pragma unroll
    for (int d = 1; d < 256; d <<= 1) {
        int u = (t >= d) ? s[t - d] : 0;
        __syncthreads();
        s[t] += u;
        __syncthreads();
    }
    g_off[i] = s[t] - v;                 // exclusive within tile
    if (t == 255) g_bsum[blockIdx.x] = s[255];
}
// phase B: scan the 1024 tile totals (1 block, 1024 threads)
__global__ void scanB() {
    __shared__ int s[NTILE];
    int t = threadIdx.x;
    int v = g_bsum[t];
    s[t] = v;
    __syncthreads();
#pragma unroll
    for (int d = 1; d < NTILE; d <<= 1) {
        int u = (t >= d) ? s[t - d] : 0;
        __syncthreads();
        s[t] += u;
        __syncthreads();
    }
    g_boff[t] = s[t] - v;                // exclusive tile offset
}
// phase C: add tile offsets
__global__ void scanC() {
    int i = blockIdx.x * 256 + threadIdx.x;
    g_off[i] += g_boff[blockIdx.x];
}
// scatter sorted point records + per-point validity masks
__global__ void scatter_kernel(const float* __restrict__ x,
                               const float* __restrict__ gscale,
                               const float* __restrict__ gtrans) {
    __shared__ float sc[192], tr[192];
    const int tid = threadIdx.x;
    for (int i = tid; i < 192; i += 256) {
        sc[i] = gscale[i];
        tr[i] = gtrans[i];
    }
    __syncthreads();
    int pt = blockIdx.x * blockDim.x + tid;
    float px = x[3 * pt], py = x[3 * pt + 1], pz = x[3 * pt + 2];
    int k = morton_key(px, py, pz);
    int pos = atomicAdd(&g_off[k], 1);
    g_xs[pos] = make_float4(px, py, pz, __int_as_float(pt));
    unsigned long long mask = 0ull;
#pragma unroll 1
    for (int g = 0; g < 64; g++) {
        float ix = fmaf(fmaf(px, sc[3 * g + 0], tr[3 * g + 0]), 31.5f, 31.5f);
        float iy = fmaf(fmaf(py, sc[3 * g + 1], tr[3 * g + 1]), 31.5f, 31.5f);
        float iz = fmaf(fmaf(pz, sc[3 * g + 2], tr[3 * g + 2]), 31.5f, 31.5f);
        if (ix > -1.f && ix < 64.f && iy > -1.f && iy < 64.f && iz > -1.f &&
            iz < 64.f)
            mask |= 1ull << g;
    }
    g_msort[pos] = mask;
}

// ---------------- smem layout (floats), identical to R14 ----------------
#define OFF_PE   0                        // 36*64 = 2304
#define OFF_W0G  (OFF_PE + 36 * 64)       // 64*132 = 8448
#define OFF_W1T  (OFF_W0G + 64 * 132)     // 64*64 = 4096
#define OFF_W2   (OFF_W1T + 64 * 64)      // 64
#define OFF_B1   (OFF_W2 + 64)            // 64
#define OFF_B0   (OFF_B1 + 64)            // 64
#define OFF_GP   (OFF_B0 + 64)            // 512
#define SMEM_FLOATS (OFF_GP + 512)
#define SMEM_BYTES  (SMEM_FLOATS * 4)     // ~62 KB -> 2 CTAs/SM

__global__ void __launch_bounds__(THREADS, 2)
amrsrn_main(const float* __restrict__ x,
            const float* __restrict__ gscale,
            const float* __restrict__ gtrans,
            const float* __restrict__ W0,
            const float* __restrict__ b0,
            const float* __restrict__ W1,
            const float* __restrict__ b1,
            const float* __restrict__ W2,
            const float* __restrict__ b2,
            float* __restrict__ out) {
    extern __shared__ float sm[];
    int tid = threadIdx.x;

    // ---- stage weights ----
    for (int i = tid; i < 36 * 64; i += THREADS) sm[OFF_PE + i] = W0[i];
    for (int i = tid; i < 64 * 128; i += THREADS) {
        int g = i >> 7, j = i & 127;
        int row = 36 + 2 * g + (j >> 6);
        sm[OFF_W0G + g * 132 + j] = W0[row * 64 + (j & 63)];
    }
    for (int i = tid; i < 64 * 64; i += THREADS) {   // transpose W1 -> [k][j]
        int j = i >> 6, k = i & 63;
        sm[OFF_W1T + k * 64 + j] = W1[i];
    }
    for (int i = tid; i < 64; i += THREADS) {
        sm[OFF_W2 + i] = W2[i];
        sm[OFF_B1 + i] = b1[i];
        sm[OFF_B0 + i] = b0[i];
    }
    for (int i = tid; i < 64; i += THREADS) {
        sm[OFF_GP + i * 8 + 0] = gscale[3 * i + 0];
        sm[OFF_GP + i * 8 + 1] = gscale[3 * i + 1];
        sm[OFF_GP + i * 8 + 2] = gscale[3 * i + 2];
        sm[OFF_GP + i * 8 + 3] = gtrans[3 * i + 0];
        sm[OFF_GP + i * 8 + 4] = gtrans[3 * i + 1];
        sm[OFF_GP + i * 8 + 5] = gtrans[3 * i + 2];
        sm[OFF_GP + i * 8 + 6] = 0.f;
        sm[OFF_GP + i * 8 + 7] = 0.f;
    }
    __syncthreads();

    const int slot = blockIdx.x * PTS_CTA + tid;
    const float4 xp = __ldg(&g_xs[slot]);           // coalesced LDG.128
    unsigned long long mask = __ldg(&g_msort[slot]); // coalesced LDG.64
    const int pt = __float_as_int(xp.w);
    const float px = xp.x;
    const float py = xp.y;
    const float pz = xp.z;
    const float xyz[3] = {px, py, pz};
    const float4* gp4 = (const float4*)&sm[OFF_GP];

    // ---- h0 accumulators (32 packed f32x2), init = b0 ----
    unsigned long long acc[32];
    const unsigned long long* pb0 =
        reinterpret_cast<const unsigned long long*>(&sm[OFF_B0]);
#pragma unroll
    for (int i = 0; i < 32; i++) acc[i] = pb0[i];

    // ---- PE via double-angle recurrence (smem broadcast rows) ----
#pragma unroll
    for (int d = 0; d < 3; d++) {
        float s, c;
        sincosf(xyz[d] * 3.14159265358979323846f, &s, &c);
#pragma unroll
        for (int l = 0; l < PE_L; l++) {
            accum_row_s(acc, &sm[OFF_PE + (l * 3 + d) * 64], s);
            accum_row_s(acc, &sm[OFF_PE + (18 + l * 3 + d) * 64], c);
            float s2 = 2.f * s * c;
            float c2 = fmaf(-2.f * s, s, 1.f);
            s = s2;
            c = c2;
        }
    }

    // ---- compacted sparse gather + accumulation (mask precomputed) ----
    while (mask) {
        int g = __ffsll((long long)mask) - 1;
        mask &= mask - 1;
        float4 p1 = gp4[g * 2];
        float4 p2 = gp4[g * 2 + 1];
        float ix = fmaf(fmaf(px, p1.x, p1.w), 31.5f, 31.5f);
        float iy = fmaf(fmaf(py, p1.y, p2.x), 31.5f, 31.5f);
        float iz = fmaf(fmaf(pz, p1.z, p2.y), 31.5f, 31.5f);
        float fx = floorf(ix), fy = floorf(iy), fz = floorf(iz);
        int X0 = (int)fx, Y0 = (int)fy, Z0 = (int)fz;
        float wx1 = ix - fx, wy1 = iy - fy, wz1 = iz - fz;
        float wx0 = 1.f - wx1, wy0 = 1.f - wy1, wz0 = 1.f - wz1;
        int bx = X0;
        float wa = wx0, wb = wx1;
        if (X0 < 0)        { bx = 0; wa = wx1; wb = 0.f; }
        else if (X0 >= 63) { wb = 0.f; }
        if (Y0 < 0)   wy0 = 0.f;
        if (Y0 >= 63) wy1 = 0.f;
        if (Z0 < 0)   wz0 = 0.f;
        if (Z0 >= 63) wz1 = 0.f;
        int y0c = max(Y0, 0), y1c = min(Y0 + 1, 63);
        int z0c = max(Z0, 0), z1c = min(Z0 + 1, 63);

        const float4* vol = g_dupx + ((size_t)g << 18);
        float4 q00 = __ldg(&vol[(z0c << 12) + (y0c << 6) + bx]);
        float4 q01 = __ldg(&vol[(z0c << 12) + (y1c << 6) + bx]);
        float4 q10 = __ldg(&vol[(z1c << 12) + (y0c << 6) + bx]);
        float4 q11 = __ldg(&vol[(z1c << 12) + (y1c << 6) + bx]);

        float w00 = wz0 * wy0, w01 = wz0 * wy1;
        float w10 = wz1 * wy0, w11 = wz1 * wy1;

        float r00 = fmaf(wb, q00.z, wa * q00.x);
        float r01 = fmaf(wb, q01.z, wa * q01.x);
        float r10 = fmaf(wb, q10.z, wa * q10.x);
        float r11 = fmaf(wb, q11.z, wa * q11.x);
        float f0 = w00 * r00;
        f0 = fmaf(w01, r01, f0);
        f0 = fmaf(w10, r10, f0);
        f0 = fmaf(w11, r11, f0);

        float s00 = fmaf(wb, q00.w, wa * q00.y);
        float s01 = fmaf(wb, q01.w, wa * q01.y);
        float s10 = fmaf(wb, q10.w, wa * q10.y);
        float s11 = fmaf(wb, q11.w, wa * q11.y);
        float f1 = w00 * s00;
        f1 = fmaf(w01, s01, f1);
        f1 = fmaf(w10, s10, f1);
        f1 = fmaf(w11, s11, f1);

        const float* wrow = &sm[OFF_W0G + g * 132];
        accum_row_s(acc, wrow, f0);
        accum_row_s(acc, wrow + 64, f1);
    }

    // ---- snake activation on h0 ----
#pragma unroll
    for (int i = 0; i < 32; i++) {
        float2 h = unpack2(acc[i]);
        float s0 = __sinf(h.x), s1 = __sinf(h.y);
        acc[i] = pack2(fmaf(0.5f, h.x, s0 * s0), fmaf(0.5f, h.y, s1 * s1));
    }

    // ---- layer1 (smem broadcast W1T rows) + snake + layer2 ----
    float outv = 0.f;
#pragma unroll 1
    for (int k = 0; k < 64; k++) {
        const ulonglong2* r2 =
            reinterpret_cast<const ulonglong2*>(&sm[OFF_W1T + k * 64]);
        unsigned long long a0 = 0ull, a1 = 0ull, a2 = 0ull, a3 = 0ull;
#pragma unroll
        for (int j = 0; j < 8; j++) {
            ulonglong2 wA = r2[2 * j];
            ulonglong2 wB = r2[2 * j + 1];
            fma2(a0, acc[4 * j + 0], wA.x);
            fma2(a1, acc[4 * j + 1], wA.y);
            fma2(a2, acc[4 * j + 2], wB.x);
            fma2(a3, acc[4 * j + 3], wB.y);
        }
        float2 fa = unpack2(a0), fb = unpack2(a1), fc = unpack2(a2),
               fd = unpack2(a3);
        float h = ((fa.x + fa.y) + (fb.x + fb.y)) +
                  ((fc.x + fc.y) + (fd.x + fd.y)) + sm[OFF_B1 + k];
        float s = __sinf(h);
        outv = fmaf(fmaf(0.5f, h, s * s), sm[OFF_W2 + k], outv);
    }

    out[pt] = outv + __ldg(b2);
}

extern "C" void kernel_launch(void* const* d_in, const int* in_sizes, int n_in,
                              void* d_out, int out_size) {
    const float* x      = (const float*)d_in[0];
    const float* gsc    = (const float*)d_in[1];
    const float* gtr    = (const float*)d_in[2];
    const float* fgrids = (const float*)d_in[3];
    const float* W0     = (const float*)d_in[4];
    const float* b0     = (const float*)d_in[5];
    const float* W1     = (const float*)d_in[6];
    const float* b1     = (const float*)d_in[7];
    const float* W2     = (const float*)d_in[8];
    const float* b2     = (const float*)d_in[9];
    float* out          = (float*)d_out;

    cudaFuncSetAttribute(amrsrn_main,
                         cudaFuncAttributeMaxDynamicSharedMemorySize,
                         SMEM_BYTES);

    repack_dup<<<(NGRIDS * GVOX) / 256, 256>>>(fgrids);
    zero_hist<<<NBUCK / 256, 256>>>();
    hist_kernel<<<NPTS / 256, 256>>>(x);
    scanA<<<NTILE, 256>>>();
    scanB<<<1, NTILE>>>();
    scanC<<<NTILE, 256>>>();
    scatter_kernel<<<NPTS / 256, 256>>>(x, gsc, gtr);
    amrsrn_main<<<NPTS / PTS_CTA, THREADS, SMEM_BYTES>>>(x, gsc, gtr, W0, b0,
                                                         W1, b1, W2, b2, out);
}